// round 6
// baseline (speedup 1.0000x reference)
#include <cuda_runtime.h>
#include <cstdint>

#define DD   768
#define LSEQ 512
#define BATCH 4
#define WW   12
#define NROW (BATCH * LSEQ)      /* 2048  */
#define NOUT (NROW * WW)         /* 24576 */

// ---------------- device scratch (no allocation allowed) ----------------
__device__ float g_proj[NROW * 2 * DD];          // relu(h@proj_w^T + proj_b)
__device__ float g_A1[NROW * DD];                // relu(start_rep) @ W1^T
__device__ float g_A2[NROW * DD];                // relu(end_rep)   @ W2^T
__device__ float g_cwt[WW * DD * DD];            // conv_w transposed: [k][o][c]
__device__ float g_conv[(size_t)NOUT * DD];      // conv cumsum (raw)
__device__ int   g_span[NOUT * 2];               // clipped int32 span indices
__device__ unsigned int g_or;                    // dtype-detect flag

// ---------------- span dtype detect: OR of odd 32-bit words ----------------
// First 2*NOUT words are in-bounds for both int32 (len 2*NOUT) and int64
// (len 4*NOUT) interpretations. int64 high halves (odd words) are all zero
// since values lie in [0, 512). int32 odd words are random indices -> OR != 0.
__global__ void detect_span(const unsigned int* __restrict__ w) {
    __shared__ unsigned int red[256];
    unsigned int local = 0;
    for (int i = threadIdx.x; i < NOUT; i += 256)
        local |= w[2 * i + 1];
    red[threadIdx.x] = local;
    __syncthreads();
    for (int s = 128; s > 0; s >>= 1) {
        if (threadIdx.x < s) red[threadIdx.x] |= red[threadIdx.x + s];
        __syncthreads();
    }
    if (threadIdx.x == 0) g_or = red[0];
}

// ---------------- span convert: (int64|int32) -> clipped int32 ----------------
__global__ void convert_span(const unsigned int* __restrict__ w, int* __restrict__ out) {
    int r = blockIdx.x * blockDim.x + threadIdx.x;
    if (r >= 2 * NOUT) return;
    const bool is64 = (g_or == 0u);
    int iv = (int)(is64 ? w[2 * r] : w[r]);
    iv = iv < 0 ? 0 : (iv > LSEQ - 1 ? LSEQ - 1 : iv);
    out[r] = iv;
}

// ---------------- conv_w transpose: [o][c][k] -> [k][o][c] ----------------
__global__ void transpose_convw(const float* __restrict__ cw, float* __restrict__ out) {
    int idx = blockIdx.x * blockDim.x + threadIdx.x;   // over (o,c): 768*768
    if (idx >= DD * DD) return;
    int c = idx % DD;
    int o = idx / DD;
    const float* src = cw + (size_t)idx * WW;
    #pragma unroll
    for (int k = 0; k < WW; k++)
        out[(size_t)k * DD * DD + (size_t)o * DD + c] = src[k];
}

// ---------------- in-place cumsum over k for each (b,l,c) ----------------
__global__ void cumsum_kernel(float* __restrict__ conv) {
    int idx = blockIdx.x * blockDim.x + threadIdx.x;
    if (idx >= NROW * (DD / 4)) return;
    int c4  = idx % (DD / 4);
    int row = idx / (DD / 4);
    float4* p = reinterpret_cast<float4*>(conv + (size_t)row * WW * DD) + c4;
    float4 acc = make_float4(0.f, 0.f, 0.f, 0.f);
    #pragma unroll
    for (int k = 0; k < WW; k++) {
        float4 v = p[k * (DD / 4)];
        acc.x += v.x; acc.y += v.y; acc.z += v.z; acc.w += v.w;
        p[k * (DD / 4)] = acc;
    }
}

// ---------------- tiled NT SGEMM: C[m,n] = sum_k A[m,k]*B[n,k] ----------------
// 128x128 tile, K fixed at 768, TK=8, 256 threads, 8x8 per thread.
// KIND 0: epilogue relu(x + bias[n])                      (proj)
// KIND 1: plain store                                     (A1 / A2)
// KIND 2: A rows shifted by k with zero-pad, strided C    (conv contrib)
// KIND 3: relu on A load; epilogue relu(x + A1[g] + A2[g] + bias), C = d_out
template<int KIND>
__global__ void __launch_bounds__(256, 2)
gemm_k(const float* __restrict__ A, int lda,
       const float* __restrict__ B, int ldb,
       float* __restrict__ C, int ldc,
       const float* __restrict__ bias,
       const float* __restrict__ A1,
       const float* __restrict__ A2,
       const int* __restrict__ span)
{
    __shared__ float As[8][128];
    __shared__ float Bs[8][128];

    const int tid = threadIdx.x;
    const int m0  = blockIdx.y * 128;
    const int n0  = blockIdx.x * 128;

    const float* Ap = A;
    const float* Bp = B;
    float*       Cp = C;
    int shift = 0;
    if (KIND == 2) {
        const int b = blockIdx.z / WW;
        const int k = blockIdx.z % WW;
        Ap = A + (size_t)b * LSEQ * DD;
        Bp = B + (size_t)k * DD * DD;
        Cp = C + (size_t)b * LSEQ * WW * DD + (size_t)k * DD;
        shift = k;
    }

    const int lr = tid >> 1;          // 0..127: tile row being loaded
    const int lk = (tid & 1) << 2;    // 0 or 4: k sub-offset
    const int ty = tid >> 4;          // 0..15
    const int tx = tid & 15;          // 0..15

    float acc[8][8];
    #pragma unroll
    for (int i = 0; i < 8; i++)
        #pragma unroll
        for (int j = 0; j < 8; j++)
            acc[i][j] = 0.f;

    for (int k0 = 0; k0 < DD; k0 += 8) {
        float4 av, bv;
        if (KIND == 2) {
            int hr = m0 + lr + shift;
            if (hr < LSEQ)
                av = *(const float4*)(Ap + (size_t)hr * lda + k0 + lk);
            else
                av = make_float4(0.f, 0.f, 0.f, 0.f);
        } else {
            av = *(const float4*)(Ap + (size_t)(m0 + lr) * lda + k0 + lk);
            if (KIND == 3) {
                av.x = fmaxf(av.x, 0.f); av.y = fmaxf(av.y, 0.f);
                av.z = fmaxf(av.z, 0.f); av.w = fmaxf(av.w, 0.f);
            }
        }
        bv = *(const float4*)(Bp + (size_t)(n0 + lr) * ldb + k0 + lk);

        __syncthreads();
        As[lk + 0][lr] = av.x; As[lk + 1][lr] = av.y;
        As[lk + 2][lr] = av.z; As[lk + 3][lr] = av.w;
        Bs[lk + 0][lr] = bv.x; Bs[lk + 1][lr] = bv.y;
        Bs[lk + 2][lr] = bv.z; Bs[lk + 3][lr] = bv.w;
        __syncthreads();

        #pragma unroll
        for (int kk = 0; kk < 8; kk++) {
            float a[8], b[8];
            *(float4*)(a)     = *(const float4*)(&As[kk][ty * 8]);
            *(float4*)(a + 4) = *(const float4*)(&As[kk][ty * 8 + 4]);
            *(float4*)(b)     = *(const float4*)(&Bs[kk][tx * 8]);
            *(float4*)(b + 4) = *(const float4*)(&Bs[kk][tx * 8 + 4]);
            #pragma unroll
            for (int i = 0; i < 8; i++)
                #pragma unroll
                for (int j = 0; j < 8; j++)
                    acc[i][j] = fmaf(a[i], b[j], acc[i][j]);
        }
    }

    const int col = n0 + tx * 8;

    if (KIND == 0) {
        float bb[8];
        {
            float4 t0 = *(const float4*)(bias + col);
            float4 t1 = *(const float4*)(bias + col + 4);
            bb[0] = t0.x; bb[1] = t0.y; bb[2] = t0.z; bb[3] = t0.w;
            bb[4] = t1.x; bb[5] = t1.y; bb[6] = t1.z; bb[7] = t1.w;
        }
        #pragma unroll
        for (int i = 0; i < 8; i++) {
            int row = m0 + ty * 8 + i;
            float4 v0 = make_float4(fmaxf(acc[i][0] + bb[0], 0.f), fmaxf(acc[i][1] + bb[1], 0.f),
                                    fmaxf(acc[i][2] + bb[2], 0.f), fmaxf(acc[i][3] + bb[3], 0.f));
            float4 v1 = make_float4(fmaxf(acc[i][4] + bb[4], 0.f), fmaxf(acc[i][5] + bb[5], 0.f),
                                    fmaxf(acc[i][6] + bb[6], 0.f), fmaxf(acc[i][7] + bb[7], 0.f));
            *(float4*)(Cp + (size_t)row * ldc + col)     = v0;
            *(float4*)(Cp + (size_t)row * ldc + col + 4) = v1;
        }
    } else if (KIND == 1 || KIND == 2) {
        #pragma unroll
        for (int i = 0; i < 8; i++) {
            int row = m0 + ty * 8 + i;
            float4 v0 = make_float4(acc[i][0], acc[i][1], acc[i][2], acc[i][3]);
            float4 v1 = make_float4(acc[i][4], acc[i][5], acc[i][6], acc[i][7]);
            *(float4*)(Cp + (size_t)row * ldc + col)     = v0;
            *(float4*)(Cp + (size_t)row * ldc + col + 4) = v1;
        }
    } else { // KIND 3: final output
        float bb[8];
        {
            float4 t0 = *(const float4*)(bias + col);
            float4 t1 = *(const float4*)(bias + col + 4);
            bb[0] = t0.x; bb[1] = t0.y; bb[2] = t0.z; bb[3] = t0.w;
            bb[4] = t1.x; bb[5] = t1.y; bb[6] = t1.z; bb[7] = t1.w;
        }
        #pragma unroll
        for (int i = 0; i < 8; i++) {
            int r = m0 + ty * 8 + i;                 // global row in [0, 24576)
            int b = r / (LSEQ * WW);
            int i0 = span[2 * r];                    // pre-clipped int32
            int i1 = span[2 * r + 1];
            const float* a1p = A1 + ((size_t)b * LSEQ + i0) * DD + col;
            const float* a2p = A2 + ((size_t)b * LSEQ + i1) * DD + col;
            float4 u0 = *(const float4*)(a1p);
            float4 u1 = *(const float4*)(a1p + 4);
            float4 w0 = *(const float4*)(a2p);
            float4 w1 = *(const float4*)(a2p + 4);
            float4 o0 = make_float4(fmaxf(acc[i][0] + u0.x + w0.x + bb[0], 0.f),
                                    fmaxf(acc[i][1] + u0.y + w0.y + bb[1], 0.f),
                                    fmaxf(acc[i][2] + u0.z + w0.z + bb[2], 0.f),
                                    fmaxf(acc[i][3] + u0.w + w0.w + bb[3], 0.f));
            float4 o1 = make_float4(fmaxf(acc[i][4] + u1.x + w1.x + bb[4], 0.f),
                                    fmaxf(acc[i][5] + u1.y + w1.y + bb[5], 0.f),
                                    fmaxf(acc[i][6] + u1.z + w1.z + bb[6], 0.f),
                                    fmaxf(acc[i][7] + u1.w + w1.w + bb[7], 0.f));
            *(float4*)(Cp + (size_t)r * ldc + col)     = o0;
            *(float4*)(Cp + (size_t)r * ldc + col + 4) = o1;
        }
    }
}

// ---------------- launch ----------------
extern "C" void kernel_launch(void* const* d_in, const int* in_sizes, int n_in,
                              void* d_out, int out_size) {
    const float*        h      = (const float*)d_in[0];
    const unsigned int* spanw  = (const unsigned int*)d_in[1];
    const float*        proj_w = (const float*)d_in[2];
    const float*        proj_b = (const float*)d_in[3];
    const float*        conv_w = (const float*)d_in[4];
    const float*        out_w  = (const float*)d_in[5];
    const float*        out_b  = (const float*)d_in[6];
    float*              out    = (float*)d_out;

    float *proj, *a1, *a2, *cwt, *conv;
    int   *span;
    cudaGetSymbolAddress((void**)&proj, g_proj);
    cudaGetSymbolAddress((void**)&a1,   g_A1);
    cudaGetSymbolAddress((void**)&a2,   g_A2);
    cudaGetSymbolAddress((void**)&cwt,  g_cwt);
    cudaGetSymbolAddress((void**)&conv, g_conv);
    cudaGetSymbolAddress((void**)&span, g_span);

    // 0) span dtype detect + convert to clipped int32
    detect_span<<<1, 256>>>(spanw);
    convert_span<<<(2 * NOUT + 255) / 256, 256>>>(spanw, span);

    // 1) transpose conv_w -> [k][o][c]
    transpose_convw<<<(DD * DD + 255) / 256, 256>>>(conv_w, cwt);

    // 2) proj = relu(h @ proj_w^T + proj_b)   (2048 x 1536, K=768)
    gemm_k<0><<<dim3(2 * DD / 128, NROW / 128), 256>>>(
        h, DD, proj_w, DD, proj, 2 * DD, proj_b, nullptr, nullptr, nullptr);

    // 3) A1 = relu(start_rep) @ W1^T          (2048 x 768)
    gemm_k<1><<<dim3(DD / 128, NROW / 128), 256>>>(
        proj, 2 * DD, out_w, 3 * DD, a1, DD, nullptr, nullptr, nullptr, nullptr);

    // 4) A2 = relu(end_rep) @ W2^T            (2048 x 768)
    gemm_k<1><<<dim3(DD / 128, NROW / 128), 256>>>(
        proj + DD, 2 * DD, out_w + DD, 3 * DD, a2, DD, nullptr, nullptr, nullptr, nullptr);

    // 5) conv contribs: per (b,k) shifted GEMM (512 x 768), strided into g_conv
    gemm_k<2><<<dim3(DD / 128, LSEQ / 128, BATCH * WW), 256>>>(
        h, DD, cwt, DD, conv, WW * DD, nullptr, nullptr, nullptr, nullptr);

    // 6) in-place cumsum over k
    cumsum_kernel<<<(NROW * (DD / 4) + 255) / 256, 256>>>(conv);

    // 7) out = relu(relu(conv_cum) @ W3^T + A1[s0] + A2[s1] + out_b)  (24576 x 768)
    gemm_k<3><<<dim3(DD / 128, NOUT / 128), 256>>>(
        conv, DD, out_w + 2 * DD, 3 * DD, out, DD, out_b, a1, a2, span);
}

// round 9
// speedup vs baseline: 1.1008x; 1.1008x over previous
#include <cuda_runtime.h>
#include <cstdint>

#define DD   768
#define LSEQ 512
#define BATCH 4
#define WW   12
#define NROW (BATCH * LSEQ)      /* 2048  */
#define NOUT (NROW * WW)         /* 24576 */
#define NIT  (DD / 8)            /* 96 K-iterations */

// ---------------- device scratch (no allocation allowed) ----------------
__device__ float g_proj[NROW * 2 * DD];          // relu(h@proj_w^T + proj_b)
__device__ float g_A1[NROW * DD];                // relu(start_rep) @ W1^T
__device__ float g_A2[NROW * DD];                // relu(end_rep)   @ W2^T
__device__ float g_cwt[WW * DD * DD];            // conv_w transposed: [k][o][c]
__device__ float g_conv[(size_t)NOUT * DD];      // conv cumsum (raw)
__device__ int   g_span[NOUT * 2];               // clipped int32 span indices
__device__ unsigned int g_or;                    // dtype-detect flag

// ---------------- span dtype detect: OR of odd 32-bit words ----------------
__global__ void detect_span(const unsigned int* __restrict__ w) {
    __shared__ unsigned int red[256];
    unsigned int local = 0;
    for (int i = threadIdx.x; i < NOUT; i += 256)
        local |= w[2 * i + 1];
    red[threadIdx.x] = local;
    __syncthreads();
    for (int s = 128; s > 0; s >>= 1) {
        if (threadIdx.x < s) red[threadIdx.x] |= red[threadIdx.x + s];
        __syncthreads();
    }
    if (threadIdx.x == 0) g_or = red[0];
}

// ---------------- span convert: (int64|int32) -> clipped int32 ----------------
__global__ void convert_span(const unsigned int* __restrict__ w, int* __restrict__ out) {
    int r = blockIdx.x * blockDim.x + threadIdx.x;
    if (r >= 2 * NOUT) return;
    const bool is64 = (g_or == 0u);
    int iv = (int)(is64 ? w[2 * r] : w[r]);
    iv = iv < 0 ? 0 : (iv > LSEQ - 1 ? LSEQ - 1 : iv);
    out[r] = iv;
}

// ---------------- conv_w transpose: [o][c][k] -> [k][o][c] ----------------
__global__ void transpose_convw(const float* __restrict__ cw, float* __restrict__ out) {
    int idx = blockIdx.x * blockDim.x + threadIdx.x;
    if (idx >= DD * DD) return;
    int c = idx % DD;
    int o = idx / DD;
    const float* src = cw + (size_t)idx * WW;
    #pragma unroll
    for (int k = 0; k < WW; k++)
        out[(size_t)k * DD * DD + (size_t)o * DD + c] = src[k];
}

// ---------------- in-place cumsum over k for each (b,l,c) ----------------
__global__ void cumsum_kernel(float* __restrict__ conv) {
    int idx = blockIdx.x * blockDim.x + threadIdx.x;
    if (idx >= NROW * (DD / 4)) return;
    int c4  = idx % (DD / 4);
    int row = idx / (DD / 4);
    float4* p = reinterpret_cast<float4*>(conv + (size_t)row * WW * DD) + c4;
    float4 acc = make_float4(0.f, 0.f, 0.f, 0.f);
    #pragma unroll
    for (int k = 0; k < WW; k++) {
        float4 v = p[k * (DD / 4)];
        acc.x += v.x; acc.y += v.y; acc.z += v.z; acc.w += v.w;
        p[k * (DD / 4)] = acc;
    }
}

// ---------------- double-buffered tiled NT SGEMM ----------------
// C[m,n] = sum_k A[m,k]*B[n,k]; 128x128 tile, TK=8, 256 threads, 8x8/thread.
// KIND 0: epilogue relu(x + bias[n])                         (proj)
// KIND 1: z in {0,1}: A+=z*DD, B+=z*DD, C = z? A2arg : Carg  (A1+A2 fused)
// KIND 2: A rows shifted by k with zero-pad, strided C       (conv contrib)
// KIND 3: relu on A load; epi relu(x + A1[g] + A2[g] + bias) (final, C=d_out)
template<int KIND>
__global__ void __launch_bounds__(256, 2)
gemm_k(const float* __restrict__ A, int lda,
       const float* __restrict__ B, int ldb,
       float* __restrict__ C, int ldc,
       const float* __restrict__ bias,
       const float* __restrict__ A1,
       const float* __restrict__ A2,
       const int* __restrict__ span)
{
    __shared__ float As[2][8][128];
    __shared__ float Bs[2][8][128];

    const int tid = threadIdx.x;
    const int m0  = blockIdx.y * 128;
    const int n0  = blockIdx.x * 128;

    const float* Ap = A;
    const float* Bp = B;
    float*       Cp = C;
    int shift = 0;
    if (KIND == 2) {
        const int b = blockIdx.z / WW;
        const int k = blockIdx.z % WW;
        Ap = A + (size_t)b * LSEQ * DD;
        Bp = B + (size_t)k * DD * DD;
        Cp = C + (size_t)b * LSEQ * WW * DD + (size_t)k * DD;
        shift = k;
    }
    if (KIND == 1) {
        const int z = blockIdx.z;
        Ap = A + z * DD;
        Bp = B + z * DD;
        Cp = (z == 0) ? C : const_cast<float*>(A2);
    }

    const int lr = tid >> 1;          // 0..127: tile row being loaded
    const int lk = (tid & 1) << 2;    // 0 or 4: k sub-offset
    const int ty = tid >> 4;          // 0..15
    const int tx = tid & 15;          // 0..15

    // precomputed load bases
    const float* Arow;
    bool a_valid = true;
    if (KIND == 2) {
        int hr = m0 + lr + shift;
        a_valid = (hr < LSEQ);
        Arow = Ap + (size_t)(a_valid ? hr : 0) * lda + lk;
    } else {
        Arow = Ap + (size_t)(m0 + lr) * lda + lk;
    }
    const float* Brow = Bp + (size_t)(n0 + lr) * ldb + lk;

    auto ldA = [&](int k0) -> float4 {
        float4 v;
        if (KIND == 2) {
            if (a_valid) v = *(const float4*)(Arow + k0);
            else         v = make_float4(0.f, 0.f, 0.f, 0.f);
        } else {
            v = *(const float4*)(Arow + k0);
            if (KIND == 3) {
                v.x = fmaxf(v.x, 0.f); v.y = fmaxf(v.y, 0.f);
                v.z = fmaxf(v.z, 0.f); v.w = fmaxf(v.w, 0.f);
            }
        }
        return v;
    };
    auto ldB = [&](int k0) -> float4 {
        return *(const float4*)(Brow + k0);
    };

    float acc[8][8];
    #pragma unroll
    for (int i = 0; i < 8; i++)
        #pragma unroll
        for (int j = 0; j < 8; j++)
            acc[i][j] = 0.f;

    auto store_tile = [&](int buf, float4 av, float4 bv) {
        As[buf][lk + 0][lr] = av.x; As[buf][lk + 1][lr] = av.y;
        As[buf][lk + 2][lr] = av.z; As[buf][lk + 3][lr] = av.w;
        Bs[buf][lk + 0][lr] = bv.x; Bs[buf][lk + 1][lr] = bv.y;
        Bs[buf][lk + 2][lr] = bv.z; Bs[buf][lk + 3][lr] = bv.w;
    };
    auto compute = [&](int buf) {
        #pragma unroll
        for (int kk = 0; kk < 8; kk++) {
            float a[8], b[8];
            *(float4*)(a)     = *(const float4*)(&As[buf][kk][ty * 8]);
            *(float4*)(a + 4) = *(const float4*)(&As[buf][kk][ty * 8 + 4]);
            *(float4*)(b)     = *(const float4*)(&Bs[buf][kk][tx * 8]);
            *(float4*)(b + 4) = *(const float4*)(&Bs[buf][kk][tx * 8 + 4]);
            #pragma unroll
            for (int i = 0; i < 8; i++)
                #pragma unroll
                for (int j = 0; j < 8; j++)
                    acc[i][j] = fmaf(a[i], b[j], acc[i][j]);
        }
    };

    // prologue: tile 0 -> buf 0
    store_tile(0, ldA(0), ldB(0));
    __syncthreads();

    // main loop: unrolled x2 to keep buffer indices static
    for (int it = 0; it < NIT; it += 2) {
        // phase A: compute buf0, prefetch+store tile it+1 -> buf1
        {
            float4 av = ldA((it + 1) * 8);     // always valid: it+1 <= 95
            float4 bv = ldB((it + 1) * 8);
            compute(0);
            store_tile(1, av, bv);
            __syncthreads();
        }
        // phase B: compute buf1, prefetch+store tile it+2 -> buf0 (if any)
        if (it + 2 < NIT) {
            float4 av = ldA((it + 2) * 8);
            float4 bv = ldB((it + 2) * 8);
            compute(1);
            store_tile(0, av, bv);
            __syncthreads();
        } else {
            compute(1);
        }
    }

    const int col = n0 + tx * 8;

    if (KIND == 0) {
        float bb[8];
        {
            float4 t0 = *(const float4*)(bias + col);
            float4 t1 = *(const float4*)(bias + col + 4);
            bb[0] = t0.x; bb[1] = t0.y; bb[2] = t0.z; bb[3] = t0.w;
            bb[4] = t1.x; bb[5] = t1.y; bb[6] = t1.z; bb[7] = t1.w;
        }
        #pragma unroll
        for (int i = 0; i < 8; i++) {
            int row = m0 + ty * 8 + i;
            float4 v0 = make_float4(fmaxf(acc[i][0] + bb[0], 0.f), fmaxf(acc[i][1] + bb[1], 0.f),
                                    fmaxf(acc[i][2] + bb[2], 0.f), fmaxf(acc[i][3] + bb[3], 0.f));
            float4 v1 = make_float4(fmaxf(acc[i][4] + bb[4], 0.f), fmaxf(acc[i][5] + bb[5], 0.f),
                                    fmaxf(acc[i][6] + bb[6], 0.f), fmaxf(acc[i][7] + bb[7], 0.f));
            *(float4*)(Cp + (size_t)row * ldc + col)     = v0;
            *(float4*)(Cp + (size_t)row * ldc + col + 4) = v1;
        }
    } else if (KIND == 1 || KIND == 2) {
        #pragma unroll
        for (int i = 0; i < 8; i++) {
            int row = m0 + ty * 8 + i;
            float4 v0 = make_float4(acc[i][0], acc[i][1], acc[i][2], acc[i][3]);
            float4 v1 = make_float4(acc[i][4], acc[i][5], acc[i][6], acc[i][7]);
            *(float4*)(Cp + (size_t)row * ldc + col)     = v0;
            *(float4*)(Cp + (size_t)row * ldc + col + 4) = v1;
        }
    } else { // KIND 3: final output
        float bb[8];
        {
            float4 t0 = *(const float4*)(bias + col);
            float4 t1 = *(const float4*)(bias + col + 4);
            bb[0] = t0.x; bb[1] = t0.y; bb[2] = t0.z; bb[3] = t0.w;
            bb[4] = t1.x; bb[5] = t1.y; bb[6] = t1.z; bb[7] = t1.w;
        }
        #pragma unroll
        for (int i = 0; i < 8; i++) {
            int r = m0 + ty * 8 + i;
            int b = r / (LSEQ * WW);
            int i0 = span[2 * r];
            int i1 = span[2 * r + 1];
            const float* a1p = A1 + ((size_t)b * LSEQ + i0) * DD + col;
            const float* a2p = A2 + ((size_t)b * LSEQ + i1) * DD + col;
            float4 u0 = *(const float4*)(a1p);
            float4 u1 = *(const float4*)(a1p + 4);
            float4 w0 = *(const float4*)(a2p);
            float4 w1 = *(const float4*)(a2p + 4);
            float4 o0 = make_float4(fmaxf(acc[i][0] + u0.x + w0.x + bb[0], 0.f),
                                    fmaxf(acc[i][1] + u0.y + w0.y + bb[1], 0.f),
                                    fmaxf(acc[i][2] + u0.z + w0.z + bb[2], 0.f),
                                    fmaxf(acc[i][3] + u0.w + w0.w + bb[3], 0.f));
            float4 o1 = make_float4(fmaxf(acc[i][4] + u1.x + w1.x + bb[4], 0.f),
                                    fmaxf(acc[i][5] + u1.y + w1.y + bb[5], 0.f),
                                    fmaxf(acc[i][6] + u1.z + w1.z + bb[6], 0.f),
                                    fmaxf(acc[i][7] + u1.w + w1.w + bb[7], 0.f));
            *(float4*)(Cp + (size_t)r * ldc + col)     = o0;
            *(float4*)(Cp + (size_t)r * ldc + col + 4) = o1;
        }
    }
}

// ---------------- launch ----------------
extern "C" void kernel_launch(void* const* d_in, const int* in_sizes, int n_in,
                              void* d_out, int out_size) {
    const float*        h      = (const float*)d_in[0];
    const unsigned int* spanw  = (const unsigned int*)d_in[1];
    const float*        proj_w = (const float*)d_in[2];
    const float*        proj_b = (const float*)d_in[3];
    const float*        conv_w = (const float*)d_in[4];
    const float*        out_w  = (const float*)d_in[5];
    const float*        out_b  = (const float*)d_in[6];
    float*              out    = (float*)d_out;

    float *proj, *a1, *a2, *cwt, *conv;
    int   *span;
    cudaGetSymbolAddress((void**)&proj, g_proj);
    cudaGetSymbolAddress((void**)&a1,   g_A1);
    cudaGetSymbolAddress((void**)&a2,   g_A2);
    cudaGetSymbolAddress((void**)&cwt,  g_cwt);
    cudaGetSymbolAddress((void**)&conv, g_conv);
    cudaGetSymbolAddress((void**)&span, g_span);

    // 0) span dtype detect + convert to clipped int32
    detect_span<<<1, 256>>>(spanw);
    convert_span<<<(2 * NOUT + 255) / 256, 256>>>(spanw, span);

    // 1) transpose conv_w -> [k][o][c]
    transpose_convw<<<(DD * DD + 255) / 256, 256>>>(conv_w, cwt);

    // 2) proj = relu(h @ proj_w^T + proj_b)   (2048 x 1536, K=768)
    gemm_k<0><<<dim3(2 * DD / 128, NROW / 128), 256>>>(
        h, DD, proj_w, DD, proj, 2 * DD, proj_b, nullptr, nullptr, nullptr);

    // 3+4) A1 = relu(start)@W1^T, A2 = relu(end)@W2^T, fused via z
    gemm_k<1><<<dim3(DD / 128, NROW / 128, 2), 256>>>(
        proj, 2 * DD, out_w, 3 * DD, a1, DD, nullptr, nullptr, a2, nullptr);

    // 5) conv contribs: per (b,k) shifted GEMM (512 x 768), strided into g_conv
    gemm_k<2><<<dim3(DD / 128, LSEQ / 128, BATCH * WW), 256>>>(
        h, DD, cwt, DD, conv, WW * DD, nullptr, nullptr, nullptr, nullptr);

    // 6) in-place cumsum over k
    cumsum_kernel<<<(NROW * (DD / 4) + 255) / 256, 256>>>(conv);

    // 7) out = relu(relu(conv_cum) @ W3^T + A1[s0] + A2[s1] + out_b)  (24576 x 768)
    gemm_k<3><<<dim3(DD / 128, NOUT / 128), 256>>>(
        conv, DD, out_w + 2 * DD, 3 * DD, out, DD, out_b, a1, a2, span);
}

// round 16
// speedup vs baseline: 2.0174x; 1.8327x over previous
#include <cuda_runtime.h>
#include <cuda_bf16.h>
#include <cstdint>

#define DD    768
#define LSEQ  512
#define BATCH 4
#define WW    12
#define NROW  2048
#define NOUT  24576
#define KP    2304          /* K' = 3*768 (A:[hi,hi,lo] x B:[hi,lo,hi]) */
#define NCH   72            /* KP / 32 k-chunks */

// ---------------- device scratch ----------------
__device__ __align__(256) __nv_bfloat16 g_hb[(size_t)NROW * KP];       // h split (A-side)
__device__ __align__(256) __nv_bfloat16 g_pwb[(size_t)2 * DD * KP];    // proj_w split (B-side)
__device__ __align__(256) __nv_bfloat16 g_projb[(size_t)NROW * 2 * KP];// relu(proj) split [r][half][KP] (A-side)
__device__ __align__(256) __nv_bfloat16 g_owb[(size_t)3 * DD * KP];    // out_w split [seg][n][KP] (B-side)
__device__ __align__(256) __nv_bfloat16 g_cwb[(size_t)WW * DD * KP];   // conv_w split [k][o][KP] (B-side)
__device__ __align__(256) __nv_bfloat16 g_convb[(size_t)NOUT * KP];    // relu(conv_cum) split (A-side)
__device__ __align__(256) float g_a1[(size_t)NROW * DD];
__device__ __align__(256) float g_a2[(size_t)NROW * DD];
__device__ __align__(256) float g_conv[(size_t)NOUT * DD];
__device__ int g_span[NOUT * 2];
__device__ unsigned int g_or;

// ---------------- baseline-PTX helpers (sm_80+, no 'a' features) ----------------
__device__ __forceinline__ uint32_t smem_u32(const void* p) {
    uint32_t a;
    asm("{ .reg .u64 t; cvta.to.shared.u64 t, %1; cvt.u32.u64 %0, t; }" : "=r"(a) : "l"(p));
    return a;
}
__device__ __forceinline__ void cpa16(uint32_t d, const void* s, uint32_t sz) {
    asm volatile("cp.async.cg.shared.global [%0], [%1], 16, %2;" :: "r"(d), "l"(s), "r"(sz) : "memory");
}
#define CPA_COMMIT() asm volatile("cp.async.commit_group;" ::: "memory")
#define CPA_WAIT1()  asm volatile("cp.async.wait_group 1;" ::: "memory")
__device__ __forceinline__ void ldsm4(uint32_t& r0, uint32_t& r1, uint32_t& r2, uint32_t& r3, uint32_t a) {
    asm volatile("ldmatrix.sync.aligned.m8n8.x4.shared.b16 {%0,%1,%2,%3}, [%4];"
                 : "=r"(r0), "=r"(r1), "=r"(r2), "=r"(r3) : "r"(a));
}
__device__ __forceinline__ void mma16816(float* c, const uint32_t* a, uint32_t b0, uint32_t b1) {
    asm volatile(
        "mma.sync.aligned.m16n8k16.row.col.f32.bf16.bf16.f32 "
        "{%0,%1,%2,%3}, {%4,%5,%6,%7}, {%8,%9}, {%0,%1,%2,%3};"
        : "+f"(c[0]), "+f"(c[1]), "+f"(c[2]), "+f"(c[3])
        : "r"(a[0]), "r"(a[1]), "r"(a[2]), "r"(a[3]), "r"(b0), "r"(b1));
}

// ---------------- split helpers ----------------
__device__ __forceinline__ void split1(float v, uint16_t& h, uint16_t& l) {
    __nv_bfloat16 hb = __float2bfloat16(v);
    __nv_bfloat16 lb = __float2bfloat16(v - __bfloat162float(hb));
    h = __bfloat16_as_ushort(hb);
    l = __bfloat16_as_ushort(lb);
}

// ---------------- span dtype detect + convert ----------------
__global__ void detect_span(const unsigned int* __restrict__ w) {
    __shared__ unsigned int red[256];
    unsigned int local = 0;
    for (int i = threadIdx.x; i < NOUT; i += 256) local |= w[2 * i + 1];
    red[threadIdx.x] = local;
    __syncthreads();
    for (int s = 128; s > 0; s >>= 1) {
        if (threadIdx.x < s) red[threadIdx.x] |= red[threadIdx.x + s];
        __syncthreads();
    }
    if (threadIdx.x == 0) g_or = red[0];
}
__global__ void convert_span(const unsigned int* __restrict__ w, int* __restrict__ out) {
    int r = blockIdx.x * blockDim.x + threadIdx.x;
    if (r >= 2 * NOUT) return;
    int iv = (int)((g_or == 0u) ? w[2 * r] : w[r]);
    iv = iv < 0 ? 0 : (iv > LSEQ - 1 ? LSEQ - 1 : iv);
    out[r] = iv;
}

// ---------------- split conversions ----------------
// BSIDE=0 (A operand): segs [hi, hi, lo]. BSIDE=1 (B operand): segs [hi, lo, hi].
template<int BSIDE>
__global__ void split3(const float* __restrict__ in, __nv_bfloat16* __restrict__ out, int total) {
    int idx = blockIdx.x * blockDim.x + threadIdx.x;
    if (idx >= total) return;
    int r = idx / 96, c8 = (idx % 96) * 8;
    const float* ip = in + (size_t)r * DD + c8;
    uint32_t hp[4], lp[4];
    #pragma unroll
    for (int q = 0; q < 4; q++) {
        uint16_t h0, l0, h1, l1;
        split1(ip[2 * q], h0, l0);
        split1(ip[2 * q + 1], h1, l1);
        hp[q] = ((uint32_t)h1 << 16) | h0;
        lp[q] = ((uint32_t)l1 << 16) | l0;
    }
    __nv_bfloat16* op = out + (size_t)r * KP + c8;
    uint4 hv = make_uint4(hp[0], hp[1], hp[2], hp[3]);
    uint4 lv = make_uint4(lp[0], lp[1], lp[2], lp[3]);
    *(uint4*)(op) = hv;
    *(uint4*)(op + DD)     = BSIDE ? lv : hv;
    *(uint4*)(op + 2 * DD) = BSIDE ? hv : lv;
}
// out_w [768][3*768] -> g_owb [seg][n][KP]  (B-side: [hi, lo, hi])
__global__ void split_ow(const float* __restrict__ in, __nv_bfloat16* __restrict__ out) {
    int idx = blockIdx.x * blockDim.x + threadIdx.x;
    if (idx >= DD * 288) return;
    int n = idx / 288, q = idx % 288;
    int s = q / 96, kh8 = (q % 96) * 8;
    const float* ip = in + (size_t)n * (3 * DD) + s * DD + kh8;
    uint32_t hp[4], lp[4];
    #pragma unroll
    for (int t = 0; t < 4; t++) {
        uint16_t h0, l0, h1, l1;
        split1(ip[2 * t], h0, l0);
        split1(ip[2 * t + 1], h1, l1);
        hp[t] = ((uint32_t)h1 << 16) | h0;
        lp[t] = ((uint32_t)l1 << 16) | l0;
    }
    __nv_bfloat16* op = out + ((size_t)s * DD + n) * KP + kh8;
    uint4 hv = make_uint4(hp[0], hp[1], hp[2], hp[3]);
    uint4 lv = make_uint4(lp[0], lp[1], lp[2], lp[3]);
    *(uint4*)(op)          = hv;
    *(uint4*)(op + DD)     = lv;   // B-side: lo in segment 1
    *(uint4*)(op + 2 * DD) = hv;   // B-side: hi in segment 2
}
// conv_w [o][c][12] -> g_cwb [k][o][KP]  (B-side: [hi, lo, hi])
__global__ void split_cw(const float* __restrict__ in, __nv_bfloat16* __restrict__ out) {
    int idx = blockIdx.x * blockDim.x + threadIdx.x;
    if (idx >= DD * 96) return;
    int o = idx / 96, c8 = (idx % 96) * 8;
    const float* ip = in + ((size_t)o * DD + c8) * WW;
    float v[8][WW];
    #pragma unroll
    for (int j = 0; j < 8; j++)
        #pragma unroll
        for (int k = 0; k < WW; k++)
            v[j][k] = ip[j * WW + k];
    #pragma unroll
    for (int k = 0; k < WW; k++) {
        uint32_t hp[4], lp[4];
        #pragma unroll
        for (int q = 0; q < 4; q++) {
            uint16_t h0, l0, h1, l1;
            split1(v[2 * q][k], h0, l0);
            split1(v[2 * q + 1][k], h1, l1);
            hp[q] = ((uint32_t)h1 << 16) | h0;
            lp[q] = ((uint32_t)l1 << 16) | l0;
        }
        __nv_bfloat16* op = out + ((size_t)k * DD + o) * KP + c8;
        uint4 hv = make_uint4(hp[0], hp[1], hp[2], hp[3]);
        uint4 lv = make_uint4(lp[0], lp[1], lp[2], lp[3]);
        *(uint4*)(op)          = hv;
        *(uint4*)(op + DD)     = lv;   // B-side
        *(uint4*)(op + 2 * DD) = hv;
    }
}
// relu + split: g_conv fp32 -> g_convb  (A-side: [hi, hi, lo])
__global__ void split_conv(const float* __restrict__ in, __nv_bfloat16* __restrict__ out) {
    int idx = blockIdx.x * blockDim.x + threadIdx.x;
    if (idx >= NOUT * 96) return;
    int r = idx / 96, c8 = (idx % 96) * 8;
    const float* ip = in + (size_t)r * DD + c8;
    uint32_t hp[4], lp[4];
    #pragma unroll
    for (int q = 0; q < 4; q++) {
        uint16_t h0, l0, h1, l1;
        split1(fmaxf(ip[2 * q], 0.f), h0, l0);
        split1(fmaxf(ip[2 * q + 1], 0.f), h1, l1);
        hp[q] = ((uint32_t)h1 << 16) | h0;
        lp[q] = ((uint32_t)l1 << 16) | l0;
    }
    __nv_bfloat16* op = out + (size_t)r * KP + c8;
    uint4 hv = make_uint4(hp[0], hp[1], hp[2], hp[3]);
    uint4 lv = make_uint4(lp[0], lp[1], lp[2], lp[3]);
    *(uint4*)(op) = hv;
    *(uint4*)(op + DD) = hv;
    *(uint4*)(op + 2 * DD) = lv;
}

// ---------------- cumsum over k ----------------
__global__ void cumsum_kernel(float* __restrict__ conv) {
    int idx = blockIdx.x * blockDim.x + threadIdx.x;
    if (idx >= NROW * (DD / 4)) return;
    int c4 = idx % (DD / 4);
    int row = idx / (DD / 4);
    float4* p = reinterpret_cast<float4*>(conv + (size_t)row * WW * DD) + c4;
    float4 acc = make_float4(0.f, 0.f, 0.f, 0.f);
    #pragma unroll
    for (int k = 0; k < WW; k++) {
        float4 v = p[k * (DD / 4)];
        acc.x += v.x; acc.y += v.y; acc.z += v.z; acc.w += v.w;
        p[k * (DD / 4)] = acc;
    }
}

// ---------------- mma.sync bf16 GEMM, 128x128 tile, K'=2304 ----------------
// C[m,n] = sum_k A[m,k]*B[n,k]; 256 thr, 8 warps (2m x 4n), warp tile 64x32.
// smem: 3 stages x (A 128x40h + B 128x40h), rows padded to 80B (conflict-free ldmatrix).
// KIND 0: proj   — epi relu(x+bias) -> A-side split store into PB (g_projb)
// KIND 1: a12    — z in {0,1}; plain fp32 store to a1/a2
// KIND 2: conv   — z=(b,k); A rows shifted with zero pad; strided fp32 C
// KIND 3: final  — epi relu(x + A1[g] + A2[g] + bias) -> C (d_out)
#define ROWB  80                 /* padded row stride, bytes */
#define ASZ   (128 * ROWB)       /* 10240 */
#define STAGE (2 * ASZ)          /* 20480 */
#define SM_TOTAL (3 * STAGE)     /* 61440 */

template<int KIND>
__global__ void __launch_bounds__(256, 2)
gemm_mma(const __nv_bfloat16* __restrict__ Abf, int lda,
         const __nv_bfloat16* __restrict__ Bbf, int ldb,
         float* __restrict__ C, int ldc,
         const float* __restrict__ bias,
         const float* __restrict__ A1f, const float* __restrict__ A2f,
         const int* __restrict__ span,
         __nv_bfloat16* __restrict__ PB)
{
    extern __shared__ char smem[];
    const uint32_t sb = smem_u32(smem);
    const int tid  = threadIdx.x;
    const int wid  = tid >> 5;
    const int lane = tid & 31;
    const int m0   = blockIdx.y * 128;
    const int n0   = blockIdx.x * 128;
    const int wm   = (wid & 1) * 64;
    const int wn   = (wid >> 1) * 32;

    int shift = 0;
    float* Cp = C;
    if (KIND == 1) {
        const int z = blockIdx.z;
        Abf += (size_t)z * KP;
        Bbf += (size_t)z * DD * KP;
        Cp = (z == 0) ? C : const_cast<float*>(A2f);
    }
    if (KIND == 2) {
        const int bz = blockIdx.z / WW;
        const int kz = blockIdx.z % WW;
        Abf += (size_t)bz * LSEQ * KP;
        Bbf += (size_t)kz * DD * KP;
        Cp = C + (size_t)bz * LSEQ * WW * DD + (size_t)kz * DD;
        shift = kz;
    }

    // ---- per-thread cp.async coords: 512 16B units per tile, 2 per thread ----
    const char* srcA[2]; const char* srcB[2];
    uint32_t dstA[2], dstB[2], szA[2];
    #pragma unroll
    for (int i = 0; i < 2; i++) {
        int u = tid + 256 * i;
        int row = u >> 2, cg = u & 3;
        dstA[i] = row * ROWB + cg * 16;
        dstB[i] = dstA[i];
        int ar = m0 + row + shift;
        bool av = (KIND != 2) || (ar < LSEQ);
        szA[i] = av ? 16u : 0u;
        srcA[i] = (const char*)(Abf + (size_t)(av ? ar : 0) * lda + cg * 8);
        srcB[i] = (const char*)(Bbf + (size_t)(n0 + row) * ldb + cg * 8);
    }

    // ---- ldmatrix tile-local offsets ----
    uint32_t ra[4], rb[2];
    {
        int lrow = lane & 15, lcol = (lane >> 4) << 3;   // halves
        #pragma unroll
        for (int mi = 0; mi < 4; mi++)
            ra[mi] = (uint32_t)((wm + mi * 16 + lrow) * ROWB + lcol * 2);
        #pragma unroll
        for (int p = 0; p < 2; p++)
            rb[p] = (uint32_t)(ASZ + (wn + p * 16 + lrow) * ROWB + lcol * 2);
    }

    float c[4][4][4];
    #pragma unroll
    for (int i = 0; i < 4; i++)
        #pragma unroll
        for (int j = 0; j < 4; j++)
            #pragma unroll
            for (int q = 0; q < 4; q++)
                c[i][j][q] = 0.f;

    auto load_chunk = [&](int ck, int st) {
        uint32_t ab = sb + st * STAGE;
        size_t off = (size_t)ck * 64;
        #pragma unroll
        for (int i = 0; i < 2; i++) {
            cpa16(ab + dstA[i], srcA[i] + off, szA[i]);
            cpa16(ab + ASZ + dstB[i], srcB[i] + off, 16u);
        }
    };

    // prologue: chunks 0,1
    load_chunk(0, 0); CPA_COMMIT();
    load_chunk(1, 1); CPA_COMMIT();

    for (int ck = 0; ck < NCH; ck++) {
        const int st = ck % 3;
        CPA_WAIT1();
        __syncthreads();
        if (ck + 2 < NCH) load_chunk(ck + 2, (ck + 2) % 3);
        CPA_COMMIT();

        const uint32_t ab = sb + st * STAGE;
        #pragma unroll
        for (int kk = 0; kk < 2; kk++) {          // two k16 steps per 32-chunk
            const uint32_t kof = kk * 32;          // +16 halves = 32 bytes
            uint32_t a[4][4], bq[2][4];
            #pragma unroll
            for (int mi = 0; mi < 4; mi++)
                ldsm4(a[mi][0], a[mi][1], a[mi][2], a[mi][3], ab + ra[mi] + kof);
            #pragma unroll
            for (int p = 0; p < 2; p++)
                ldsm4(bq[p][0], bq[p][1], bq[p][2], bq[p][3], ab + rb[p] + kof);
            #pragma unroll
            for (int mi = 0; mi < 4; mi++)
                #pragma unroll
                for (int p = 0; p < 2; p++) {
                    mma16816(c[mi][2 * p],     a[mi], bq[p][0], bq[p][2]);
                    mma16816(c[mi][2 * p + 1], a[mi], bq[p][1], bq[p][3]);
                }
        }
    }

    // ---- epilogue ----
    const int crow = lane >> 2;
    const int ccol = (lane & 3) << 1;

    #pragma unroll
    for (int mi = 0; mi < 4; mi++) {
        #pragma unroll
        for (int hh = 0; hh < 2; hh++) {
            const int r = m0 + wm + mi * 16 + crow + hh * 8;
            int bg = 0, i0 = 0, i1 = 0;
            if (KIND == 3) {
                bg = r / (LSEQ * WW);
                i0 = span[2 * r];
                i1 = span[2 * r + 1];
            }
            #pragma unroll
            for (int ni = 0; ni < 4; ni++) {
                const int col = n0 + wn + ni * 8 + ccol;
                const float v0 = c[mi][ni][2 * hh];
                const float v1 = c[mi][ni][2 * hh + 1];
                if (KIND == 0) {
                    const int half = (n0 >= DD) ? 1 : 0;
                    const int nh = col - half * DD;
                    const float2 bb = *(const float2*)(bias + col);
                    float w0 = fmaxf(v0 + bb.x, 0.f);
                    float w1 = fmaxf(v1 + bb.y, 0.f);
                    uint16_t h0, l0, h1, l1;
                    split1(w0, h0, l0);
                    split1(w1, h1, l1);
                    uint32_t hp = ((uint32_t)h1 << 16) | h0;
                    uint32_t lp = ((uint32_t)l1 << 16) | l0;
                    __nv_bfloat16* pr = PB + ((size_t)r * 2 + half) * KP + nh;
                    *(uint32_t*)(pr)          = hp;   // A-side: [hi, hi, lo]
                    *(uint32_t*)(pr + DD)     = hp;
                    *(uint32_t*)(pr + 2 * DD) = lp;
                } else if (KIND == 1 || KIND == 2) {
                    *(float2*)(Cp + (size_t)r * ldc + col) = make_float2(v0, v1);
                } else { // KIND 3
                    const float2 x1 = *(const float2*)(A1f + ((size_t)bg * LSEQ + i0) * DD + col);
                    const float2 x2 = *(const float2*)(A2f + ((size_t)bg * LSEQ + i1) * DD + col);
                    const float2 bb = *(const float2*)(bias + col);
                    *(float2*)(Cp + (size_t)r * ldc + col) =
                        make_float2(fmaxf(v0 + x1.x + x2.x + bb.x, 0.f),
                                    fmaxf(v1 + x1.y + x2.y + bb.y, 0.f));
                }
            }
        }
    }
}

// ---------------- launch ----------------
extern "C" void kernel_launch(void* const* d_in, const int* in_sizes, int n_in,
                              void* d_out, int out_size) {
    const float*        h      = (const float*)d_in[0];
    const unsigned int* spanw  = (const unsigned int*)d_in[1];
    const float*        proj_w = (const float*)d_in[2];
    const float*        proj_b = (const float*)d_in[3];
    const float*        conv_w = (const float*)d_in[4];
    const float*        out_w  = (const float*)d_in[5];
    const float*        out_b  = (const float*)d_in[6];
    float*              out    = (float*)d_out;

    __nv_bfloat16 *hb, *pwb, *projb, *owb, *cwb, *convb;
    float *a1, *a2, *conv;
    int *span;
    cudaGetSymbolAddress((void**)&hb,    g_hb);
    cudaGetSymbolAddress((void**)&pwb,   g_pwb);
    cudaGetSymbolAddress((void**)&projb, g_projb);
    cudaGetSymbolAddress((void**)&owb,   g_owb);
    cudaGetSymbolAddress((void**)&cwb,   g_cwb);
    cudaGetSymbolAddress((void**)&convb, g_convb);
    cudaGetSymbolAddress((void**)&a1,    g_a1);
    cudaGetSymbolAddress((void**)&a2,    g_a2);
    cudaGetSymbolAddress((void**)&conv,  g_conv);
    cudaGetSymbolAddress((void**)&span,  g_span);

    cudaFuncSetAttribute(gemm_mma<0>, cudaFuncAttributeMaxDynamicSharedMemorySize, SM_TOTAL);
    cudaFuncSetAttribute(gemm_mma<1>, cudaFuncAttributeMaxDynamicSharedMemorySize, SM_TOTAL);
    cudaFuncSetAttribute(gemm_mma<2>, cudaFuncAttributeMaxDynamicSharedMemorySize, SM_TOTAL);
    cudaFuncSetAttribute(gemm_mma<3>, cudaFuncAttributeMaxDynamicSharedMemorySize, SM_TOTAL);

    // 0) span detect/convert + operand splits
    detect_span<<<1, 256>>>(spanw);
    convert_span<<<(2 * NOUT + 255) / 256, 256>>>(spanw, span);
    split3<0><<<(NROW * 96 + 255) / 256, 256>>>(h, hb, NROW * 96);          // A-side
    split3<1><<<(2 * DD * 96 + 255) / 256, 256>>>(proj_w, pwb, 2 * DD * 96); // B-side
    split_ow<<<(DD * 288 + 255) / 256, 256>>>(out_w, owb);                   // B-side
    split_cw<<<(DD * 96 + 255) / 256, 256>>>(conv_w, cwb);                   // B-side

    // 1) proj: relu(h @ proj_w^T + b) -> A-side split into g_projb   (2048 x 1536)
    gemm_mma<0><<<dim3(12, 16), 256, SM_TOTAL>>>(
        hb, KP, pwb, KP, nullptr, 0, proj_b, nullptr, nullptr, nullptr, projb);

    // 2) A1 = relu(start)@W1^T, A2 = relu(end)@W2^T           (2048 x 768, z in {0,1})
    gemm_mma<1><<<dim3(6, 16, 2), 256, SM_TOTAL>>>(
        projb, 2 * KP, owb, KP, a1, DD, nullptr, nullptr, a2, nullptr, nullptr);

    // 3) conv contribs: per (b,k) shifted GEMM (512 x 768), strided into g_conv
    gemm_mma<2><<<dim3(6, 4, BATCH * WW), 256, SM_TOTAL>>>(
        hb, KP, cwb, KP, conv, WW * DD, nullptr, nullptr, nullptr, nullptr, nullptr);

    // 4) cumsum over k, then relu+split (A-side) -> g_convb
    cumsum_kernel<<<(NROW * (DD / 4) + 255) / 256, 256>>>(conv);
    split_conv<<<(NOUT * 96 + 255) / 256, 256>>>(conv, convb);

    // 5) out = relu(relu(conv_cum)@W3^T + A1[s0] + A2[s1] + out_b)  (24576 x 768)
    gemm_mma<3><<<dim3(6, 192), 256, SM_TOTAL>>>(
        convb, KP, owb + (size_t)2 * DD * KP, KP, out, DD, out_b, a1, a2, span, nullptr);
}

// round 17
// speedup vs baseline: 2.6613x; 1.3192x over previous
#include <cuda_runtime.h>
#include <cuda_bf16.h>
#include <cstdint>

#define DD    768
#define LSEQ  512
#define BATCH 4
#define WW    12
#define NROW  2048
#define NOUT  24576
#define K2    1536          /* [hi(768) | lo(768)] per operand row */
#define NCH   24            /* 768 / 32 k-chunks */

// ---------------- device scratch ----------------
__device__ __align__(256) __nv_bfloat16 g_hb[(size_t)NROW * K2];        // h split [hi|lo]
__device__ __align__(256) __nv_bfloat16 g_pwb[(size_t)2 * DD * K2];     // proj_w split
__device__ __align__(256) __nv_bfloat16 g_projb[(size_t)NROW * 2 * K2]; // relu(proj) [r][half][K2]
__device__ __align__(256) __nv_bfloat16 g_owb[(size_t)3 * DD * K2];     // out_w [seg][n][K2]
__device__ __align__(256) __nv_bfloat16 g_cwb[(size_t)WW * DD * K2];    // conv_w [k][o][K2]
__device__ __align__(256) __nv_bfloat16 g_convb[(size_t)NOUT * K2];     // relu(conv_cum) [row][K2]
__device__ __align__(256) float g_a1[(size_t)NROW * DD];
__device__ __align__(256) float g_a2[(size_t)NROW * DD];
__device__ __align__(256) float g_conv[(size_t)NOUT * DD];
__device__ int g_span[NOUT * 2];
__device__ unsigned int g_or;

// ---------------- baseline-PTX helpers ----------------
__device__ __forceinline__ uint32_t smem_u32(const void* p) {
    uint32_t a;
    asm("{ .reg .u64 t; cvta.to.shared.u64 t, %1; cvt.u32.u64 %0, t; }" : "=r"(a) : "l"(p));
    return a;
}
__device__ __forceinline__ void cpa16(uint32_t d, const void* s, uint32_t sz) {
    asm volatile("cp.async.cg.shared.global [%0], [%1], 16, %2;" :: "r"(d), "l"(s), "r"(sz) : "memory");
}
#define CPA_COMMIT() asm volatile("cp.async.commit_group;" ::: "memory")
#define CPA_WAIT1()  asm volatile("cp.async.wait_group 1;" ::: "memory")
__device__ __forceinline__ void ldsm4(uint32_t& r0, uint32_t& r1, uint32_t& r2, uint32_t& r3, uint32_t a) {
    asm volatile("ldmatrix.sync.aligned.m8n8.x4.shared.b16 {%0,%1,%2,%3}, [%4];"
                 : "=r"(r0), "=r"(r1), "=r"(r2), "=r"(r3) : "r"(a));
}
__device__ __forceinline__ void mma16816(float* c, const uint32_t* a, uint32_t b0, uint32_t b1) {
    asm volatile(
        "mma.sync.aligned.m16n8k16.row.col.f32.bf16.bf16.f32 "
        "{%0,%1,%2,%3}, {%4,%5,%6,%7}, {%8,%9}, {%0,%1,%2,%3};"
        : "+f"(c[0]), "+f"(c[1]), "+f"(c[2]), "+f"(c[3])
        : "r"(a[0]), "r"(a[1]), "r"(a[2]), "r"(a[3]), "r"(b0), "r"(b1));
}

// ---------------- split helpers ----------------
__device__ __forceinline__ void split1(float v, uint16_t& h, uint16_t& l) {
    __nv_bfloat16 hb = __float2bfloat16(v);
    __nv_bfloat16 lb = __float2bfloat16(v - __bfloat162float(hb));
    h = __bfloat16_as_ushort(hb);
    l = __bfloat16_as_ushort(lb);
}

// ---------------- span dtype detect + convert ----------------
__global__ void detect_span(const unsigned int* __restrict__ w) {
    __shared__ unsigned int red[256];
    unsigned int local = 0;
    for (int i = threadIdx.x; i < NOUT; i += 256) local |= w[2 * i + 1];
    red[threadIdx.x] = local;
    __syncthreads();
    for (int s = 128; s > 0; s >>= 1) {
        if (threadIdx.x < s) red[threadIdx.x] |= red[threadIdx.x + s];
        __syncthreads();
    }
    if (threadIdx.x == 0) g_or = red[0];
}
__global__ void convert_span(const unsigned int* __restrict__ w, int* __restrict__ out) {
    int r = blockIdx.x * blockDim.x + threadIdx.x;
    if (r >= 2 * NOUT) return;
    int iv = (int)((g_or == 0u) ? w[2 * r] : w[r]);
    iv = iv < 0 ? 0 : (iv > LSEQ - 1 ? LSEQ - 1 : iv);
    out[r] = iv;
}

// ---------------- split conversions: fp32 [R][768] -> [R][hi|lo] ----------------
__global__ void split2(const float* __restrict__ in, __nv_bfloat16* __restrict__ out, int total) {
    int idx = blockIdx.x * blockDim.x + threadIdx.x;
    if (idx >= total) return;
    int r = idx / 96, c8 = (idx % 96) * 8;
    const float* ip = in + (size_t)r * DD + c8;
    uint32_t hp[4], lp[4];
    #pragma unroll
    for (int q = 0; q < 4; q++) {
        uint16_t h0, l0, h1, l1;
        split1(ip[2 * q], h0, l0);
        split1(ip[2 * q + 1], h1, l1);
        hp[q] = ((uint32_t)h1 << 16) | h0;
        lp[q] = ((uint32_t)l1 << 16) | l0;
    }
    __nv_bfloat16* op = out + (size_t)r * K2 + c8;
    *(uint4*)(op)      = make_uint4(hp[0], hp[1], hp[2], hp[3]);
    *(uint4*)(op + DD) = make_uint4(lp[0], lp[1], lp[2], lp[3]);
}
// out_w [768][3*768] -> g_owb [seg][n][K2]
__global__ void split_ow(const float* __restrict__ in, __nv_bfloat16* __restrict__ out) {
    int idx = blockIdx.x * blockDim.x + threadIdx.x;
    if (idx >= DD * 288) return;
    int n = idx / 288, q = idx % 288;
    int s = q / 96, c8 = (q % 96) * 8;
    const float* ip = in + (size_t)n * (3 * DD) + s * DD + c8;
    uint32_t hp[4], lp[4];
    #pragma unroll
    for (int t = 0; t < 4; t++) {
        uint16_t h0, l0, h1, l1;
        split1(ip[2 * t], h0, l0);
        split1(ip[2 * t + 1], h1, l1);
        hp[t] = ((uint32_t)h1 << 16) | h0;
        lp[t] = ((uint32_t)l1 << 16) | l0;
    }
    __nv_bfloat16* op = out + ((size_t)s * DD + n) * K2 + c8;
    *(uint4*)(op)      = make_uint4(hp[0], hp[1], hp[2], hp[3]);
    *(uint4*)(op + DD) = make_uint4(lp[0], lp[1], lp[2], lp[3]);
}
// conv_w [o][c][12] -> g_cwb [k][o][K2]
__global__ void split_cw(const float* __restrict__ in, __nv_bfloat16* __restrict__ out) {
    int idx = blockIdx.x * blockDim.x + threadIdx.x;
    if (idx >= DD * 96) return;
    int o = idx / 96, c8 = (idx % 96) * 8;
    const float* ip = in + ((size_t)o * DD + c8) * WW;
    float v[8][WW];
    #pragma unroll
    for (int j = 0; j < 8; j++)
        #pragma unroll
        for (int k = 0; k < WW; k++)
            v[j][k] = ip[j * WW + k];
    #pragma unroll
    for (int k = 0; k < WW; k++) {
        uint32_t hp[4], lp[4];
        #pragma unroll
        for (int q = 0; q < 4; q++) {
            uint16_t h0, l0, h1, l1;
            split1(v[2 * q][k], h0, l0);
            split1(v[2 * q + 1][k], h1, l1);
            hp[q] = ((uint32_t)h1 << 16) | h0;
            lp[q] = ((uint32_t)l1 << 16) | l0;
        }
        __nv_bfloat16* op = out + ((size_t)k * DD + o) * K2 + c8;
        *(uint4*)(op)      = make_uint4(hp[0], hp[1], hp[2], hp[3]);
        *(uint4*)(op + DD) = make_uint4(lp[0], lp[1], lp[2], lp[3]);
    }
}

// ---------------- fused cumsum + relu + split: g_conv -> g_convb ----------------
__global__ void cumsum_split(const float* __restrict__ conv, __nv_bfloat16* __restrict__ out) {
    int idx = blockIdx.x * blockDim.x + threadIdx.x;
    if (idx >= NROW * (DD / 4)) return;
    int c4 = idx % (DD / 4);
    int row = idx / (DD / 4);
    const float4* p = reinterpret_cast<const float4*>(conv + (size_t)row * WW * DD) + c4;
    float4 acc = make_float4(0.f, 0.f, 0.f, 0.f);
    #pragma unroll
    for (int k = 0; k < WW; k++) {
        float4 v = p[k * (DD / 4)];
        acc.x += v.x; acc.y += v.y; acc.z += v.z; acc.w += v.w;
        uint16_t h0, l0, h1, l1, h2, l2, h3, l3;
        split1(fmaxf(acc.x, 0.f), h0, l0);
        split1(fmaxf(acc.y, 0.f), h1, l1);
        split1(fmaxf(acc.z, 0.f), h2, l2);
        split1(fmaxf(acc.w, 0.f), h3, l3);
        __nv_bfloat16* op = out + ((size_t)row * WW + k) * K2 + c4 * 4;
        *(uint2*)(op)      = make_uint2(((uint32_t)h1 << 16) | h0, ((uint32_t)h3 << 16) | h2);
        *(uint2*)(op + DD) = make_uint2(((uint32_t)l1 << 16) | l0, ((uint32_t)l3 << 16) | l2);
    }
}

// ---------------- mma.sync bf16 GEMM, 128x128 tile, dedup planes ----------------
// C[m,n] = sum_k(768) A[m,k]*B[n,k] in split precision: AhBh + AhBl + AlBh.
// 256 thr, 8 warps (2m x 4n), warp tile 64x32; K chunks of 32; 3-stage cp.async.
// smem/stage: 4 planes (Ah, Al, Bh, Bl) x 128 rows x 64B, 4-way XOR swizzle.
// KIND 0: proj   — epi relu(x+bias) -> [hi|lo] split store into PB (g_projb)
// KIND 1: a12    — z in {0,1}; plain fp32 store to a1/a2
// KIND 2: conv   — z=(b,k); A rows shifted with zero pad; strided fp32 C
// KIND 3: final  — epi relu(x + A1[g] + A2[g] + bias) -> C (d_out)
#define PLANE 8192               /* 128 rows * 64B */
#define STG   (4 * PLANE)        /* 32768 per stage */
#define SM_TOTAL (3 * STG)       /* 98304 */

template<int KIND>
__global__ void __launch_bounds__(256, 2)
gemm_mma(const __nv_bfloat16* __restrict__ Abf, int lda,
         const __nv_bfloat16* __restrict__ Bbf, int ldb,
         float* __restrict__ C, int ldc,
         const float* __restrict__ bias,
         const float* __restrict__ A1f, const float* __restrict__ A2f,
         const int* __restrict__ span,
         __nv_bfloat16* __restrict__ PB)
{
    extern __shared__ char smem[];
    const uint32_t sb = smem_u32(smem);
    const int tid  = threadIdx.x;
    const int wid  = tid >> 5;
    const int lane = tid & 31;
    const int m0   = blockIdx.y * 128;
    const int n0   = blockIdx.x * 128;
    const int wm   = (wid & 1) * 64;
    const int wn   = (wid >> 1) * 32;

    int shift = 0;
    float* Cp = C;
    if (KIND == 1) {
        const int z = blockIdx.z;
        Abf += (size_t)z * K2;               // projb [r][half][K2], lda = 2*K2
        Bbf += (size_t)z * DD * K2;
        Cp = (z == 0) ? C : const_cast<float*>(A2f);
    }
    if (KIND == 2) {
        const int bz = blockIdx.z / WW;
        const int kz = blockIdx.z % WW;
        Abf += (size_t)bz * LSEQ * K2;
        Bbf += (size_t)kz * DD * K2;
        Cp = C + (size_t)bz * LSEQ * WW * DD + (size_t)kz * DD;
        shift = kz;
    }

    // ---- cp.async coords: thread -> rows (r0, r0+64), col-group cg ----
    const int r0 = tid >> 2;
    const int cg = tid & 3;
    const uint32_t d0 = (uint32_t)(r0 * 64 + ((cg ^ ((r0 >> 1) & 3)) << 4));   // d1 = d0 + 4096

    int ar0 = m0 + r0 + shift;
    int ar1 = ar0 + 64;
    const bool av0 = (KIND != 2) || (ar0 < LSEQ);
    const bool av1 = (KIND != 2) || (ar1 < LSEQ);
    const uint32_t szA0 = av0 ? 16u : 0u;
    const uint32_t szA1 = av1 ? 16u : 0u;
    const char* sA0 = (const char*)(Abf + (size_t)(av0 ? ar0 : 0) * lda + cg * 8);
    const char* sA1 = (const char*)(Abf + (size_t)(av1 ? ar1 : 0) * lda + cg * 8);
    const char* sB0 = (const char*)(Bbf + (size_t)(n0 + r0) * ldb + cg * 8);
    const char* sB1 = (const char*)(Bbf + (size_t)(n0 + r0 + 64) * ldb + cg * 8);

    auto load_chunk = [&](int ck, int st) {
        const uint32_t ab = sb + st * STG;
        const size_t off = (size_t)ck * 64;
        cpa16(ab + d0,                 sA0 + off,        szA0);   // Ah
        cpa16(ab + d0 + 4096,          sA1 + off,        szA1);
        cpa16(ab + PLANE + d0,         sA0 + 1536 + off, szA0);   // Al (+768 elems)
        cpa16(ab + PLANE + d0 + 4096,  sA1 + 1536 + off, szA1);
        cpa16(ab + 2*PLANE + d0,       sB0 + off,        16u);    // Bh
        cpa16(ab + 2*PLANE + d0 + 4096,sB1 + off,        16u);
        cpa16(ab + 3*PLANE + d0,       sB0 + 1536 + off, 16u);    // Bl
        cpa16(ab + 3*PLANE + d0 + 4096,sB1 + 1536 + off, 16u);
    };

    // ---- ldmatrix per-lane bases ----
    const int lrow = lane & 15;
    const int lsel = lane >> 4;   // 0/1 -> 16B column half
    uint32_t ra64[4], raswz[4], rb64[2], rbswz[2];
    #pragma unroll
    for (int mi = 0; mi < 4; mi++) {
        int r = wm + mi * 16 + lrow;
        ra64[mi]  = (uint32_t)(r * 64);
        raswz[mi] = (uint32_t)((r >> 1) & 3);
    }
    #pragma unroll
    for (int p = 0; p < 2; p++) {
        int r = wn + p * 16 + lrow;
        rb64[p]  = (uint32_t)(r * 64);
        rbswz[p] = (uint32_t)((r >> 1) & 3);
    }

    float c[4][4][4];
    #pragma unroll
    for (int i = 0; i < 4; i++)
        #pragma unroll
        for (int j = 0; j < 4; j++)
            #pragma unroll
            for (int q = 0; q < 4; q++)
                c[i][j][q] = 0.f;

    // prologue
    load_chunk(0, 0); CPA_COMMIT();
    load_chunk(1, 1); CPA_COMMIT();

    for (int ck = 0; ck < NCH; ck++) {
        const int st = ck % 3;
        CPA_WAIT1();
        __syncthreads();
        if (ck + 2 < NCH) load_chunk(ck + 2, (ck + 2) % 3);
        CPA_COMMIT();

        const uint32_t ab = sb + st * STG;
        #pragma unroll
        for (int kk = 0; kk < 2; kk++) {
            const uint32_t cgx = (uint32_t)(kk * 2 + lsel);
            uint32_t a[4][4], bh[2][4], bl[2][4];
            #pragma unroll
            for (int mi = 0; mi < 4; mi++)   // Ah
                ldsm4(a[mi][0], a[mi][1], a[mi][2], a[mi][3],
                      ab + ra64[mi] + ((cgx ^ raswz[mi]) << 4));
            #pragma unroll
            for (int p = 0; p < 2; p++)      // Bh
                ldsm4(bh[p][0], bh[p][1], bh[p][2], bh[p][3],
                      ab + 2*PLANE + rb64[p] + ((cgx ^ rbswz[p]) << 4));
            #pragma unroll
            for (int p = 0; p < 2; p++)      // Bl
                ldsm4(bl[p][0], bl[p][1], bl[p][2], bl[p][3],
                      ab + 3*PLANE + rb64[p] + ((cgx ^ rbswz[p]) << 4));
            #pragma unroll
            for (int mi = 0; mi < 4; mi++)
                #pragma unroll
                for (int p = 0; p < 2; p++) {
                    mma16816(c[mi][2 * p],     a[mi], bh[p][0], bh[p][2]);
                    mma16816(c[mi][2 * p + 1], a[mi], bh[p][1], bh[p][3]);
                    mma16816(c[mi][2 * p],     a[mi], bl[p][0], bl[p][2]);
                    mma16816(c[mi][2 * p + 1], a[mi], bl[p][1], bl[p][3]);
                }
            #pragma unroll
            for (int mi = 0; mi < 4; mi++)   // Al (reuse a regs)
                ldsm4(a[mi][0], a[mi][1], a[mi][2], a[mi][3],
                      ab + PLANE + ra64[mi] + ((cgx ^ raswz[mi]) << 4));
            #pragma unroll
            for (int mi = 0; mi < 4; mi++)
                #pragma unroll
                for (int p = 0; p < 2; p++) {
                    mma16816(c[mi][2 * p],     a[mi], bh[p][0], bh[p][2]);
                    mma16816(c[mi][2 * p + 1], a[mi], bh[p][1], bh[p][3]);
                }
        }
    }

    // ---- epilogue ----
    const int crow = lane >> 2;
    const int ccol = (lane & 3) << 1;

    #pragma unroll
    for (int mi = 0; mi < 4; mi++) {
        #pragma unroll
        for (int hh = 0; hh < 2; hh++) {
            const int r = m0 + wm + mi * 16 + crow + hh * 8;
            int bg = 0, i0 = 0, i1 = 0;
            if (KIND == 3) {
                bg = r / (LSEQ * WW);
                i0 = span[2 * r];
                i1 = span[2 * r + 1];
            }
            #pragma unroll
            for (int ni = 0; ni < 4; ni++) {
                const int col = n0 + wn + ni * 8 + ccol;
                const float v0 = c[mi][ni][2 * hh];
                const float v1 = c[mi][ni][2 * hh + 1];
                if (KIND == 0) {
                    const int half = (n0 >= DD) ? 1 : 0;
                    const int nh = col - half * DD;
                    const float2 bb = *(const float2*)(bias + col);
                    float w0 = fmaxf(v0 + bb.x, 0.f);
                    float w1 = fmaxf(v1 + bb.y, 0.f);
                    uint16_t h0, l0, h1, l1;
                    split1(w0, h0, l0);
                    split1(w1, h1, l1);
                    __nv_bfloat16* pr = PB + ((size_t)r * 2 + half) * K2 + nh;
                    *(uint32_t*)(pr)      = ((uint32_t)h1 << 16) | h0;
                    *(uint32_t*)(pr + DD) = ((uint32_t)l1 << 16) | l0;
                } else if (KIND == 1 || KIND == 2) {
                    *(float2*)(Cp + (size_t)r * ldc + col) = make_float2(v0, v1);
                } else { // KIND 3
                    const float2 x1 = *(const float2*)(A1f + ((size_t)bg * LSEQ + i0) * DD + col);
                    const float2 x2 = *(const float2*)(A2f + ((size_t)bg * LSEQ + i1) * DD + col);
                    const float2 bb = *(const float2*)(bias + col);
                    *(float2*)(Cp + (size_t)r * ldc + col) =
                        make_float2(fmaxf(v0 + x1.x + x2.x + bb.x, 0.f),
                                    fmaxf(v1 + x1.y + x2.y + bb.y, 0.f));
                }
            }
        }
    }
}

// ---------------- launch ----------------
extern "C" void kernel_launch(void* const* d_in, const int* in_sizes, int n_in,
                              void* d_out, int out_size) {
    const float*        h      = (const float*)d_in[0];
    const unsigned int* spanw  = (const unsigned int*)d_in[1];
    const float*        proj_w = (const float*)d_in[2];
    const float*        proj_b = (const float*)d_in[3];
    const float*        conv_w = (const float*)d_in[4];
    const float*        out_w  = (const float*)d_in[5];
    const float*        out_b  = (const float*)d_in[6];
    float*              out    = (float*)d_out;

    __nv_bfloat16 *hb, *pwb, *projb, *owb, *cwb, *convb;
    float *a1, *a2, *conv;
    int *span;
    cudaGetSymbolAddress((void**)&hb,    g_hb);
    cudaGetSymbolAddress((void**)&pwb,   g_pwb);
    cudaGetSymbolAddress((void**)&projb, g_projb);
    cudaGetSymbolAddress((void**)&owb,   g_owb);
    cudaGetSymbolAddress((void**)&cwb,   g_cwb);
    cudaGetSymbolAddress((void**)&convb, g_convb);
    cudaGetSymbolAddress((void**)&a1,    g_a1);
    cudaGetSymbolAddress((void**)&a2,    g_a2);
    cudaGetSymbolAddress((void**)&conv,  g_conv);
    cudaGetSymbolAddress((void**)&span,  g_span);

    cudaFuncSetAttribute(gemm_mma<0>, cudaFuncAttributeMaxDynamicSharedMemorySize, SM_TOTAL);
    cudaFuncSetAttribute(gemm_mma<1>, cudaFuncAttributeMaxDynamicSharedMemorySize, SM_TOTAL);
    cudaFuncSetAttribute(gemm_mma<2>, cudaFuncAttributeMaxDynamicSharedMemorySize, SM_TOTAL);
    cudaFuncSetAttribute(gemm_mma<3>, cudaFuncAttributeMaxDynamicSharedMemorySize, SM_TOTAL);

    // 0) span detect/convert + operand splits ([hi|lo], no duplication)
    detect_span<<<1, 256>>>(spanw);
    convert_span<<<(2 * NOUT + 255) / 256, 256>>>(spanw, span);
    split2<<<(NROW * 96 + 255) / 256, 256>>>(h, hb, NROW * 96);
    split2<<<(2 * DD * 96 + 255) / 256, 256>>>(proj_w, pwb, 2 * DD * 96);
    split_ow<<<(DD * 288 + 255) / 256, 256>>>(out_w, owb);
    split_cw<<<(DD * 96 + 255) / 256, 256>>>(conv_w, cwb);

    // 1) proj: relu(h @ proj_w^T + b) -> [hi|lo] split into g_projb  (2048 x 1536)
    gemm_mma<0><<<dim3(12, 16), 256, SM_TOTAL>>>(
        hb, K2, pwb, K2, nullptr, 0, proj_b, nullptr, nullptr, nullptr, projb);

    // 2) A1 = relu(start)@W1^T, A2 = relu(end)@W2^T  (2048 x 768, z in {0,1})
    gemm_mma<1><<<dim3(6, 16, 2), 256, SM_TOTAL>>>(
        projb, 2 * K2, owb, K2, a1, DD, nullptr, nullptr, a2, nullptr, nullptr);

    // 3) conv contribs: per (b,k) shifted GEMM (512 x 768), strided into g_conv
    gemm_mma<2><<<dim3(6, 4, BATCH * WW), 256, SM_TOTAL>>>(
        hb, K2, cwb, K2, conv, WW * DD, nullptr, nullptr, nullptr, nullptr, nullptr);

    // 4) fused cumsum + relu + split -> g_convb
    cumsum_split<<<(NROW * (DD / 4) + 255) / 256, 256>>>(conv, convb);

    // 5) out = relu(relu(conv_cum)@W3^T + A1[s0] + A2[s1] + out_b)  (24576 x 768)
    gemm_mma<3><<<dim3(6, 192), 256, SM_TOTAL>>>(
        convb, K2, owb + (size_t)2 * DD * K2, K2, out, DD, out_b, a1, a2, span, nullptr);
}